// round 6
// baseline (speedup 1.0000x reference)
#include <cuda_runtime.h>
#include <cuda_fp16.h>
#include <math.h>

#define N 8192
#define D 256
#define LAMF 10.0f
#define INV_LAM 0.1f
#define NEG_LAM_LOGN (-90.109133472792885f)
#define INV_N 1.220703125e-4f     // 1/8192

#define FROWS 16
#define FBLOCKS (N / FROWS)       // 512 row-chunks / partials
#define P2 16                     // second-stage partial count

// ---- scratch (static device globals; no allocation allowed) ----
__device__ float  g_C[(size_t)N * N];   // fp32 cost matrix (final pass only)
__device__ __half g_E[(size_t)N * N];   // exp(-C/lam) fp16 (iteration passes)
__device__ float  g_f[N];
__device__ float  g_g[N];
__device__ float  g_s[N];               // row sums s_i
__device__ float  g_S[N];               // col sums S'_j
__device__ float  g_Eg[N];              // exp(g/lam) = (1/N)/S'
__device__ float  g_x2[N];
__device__ float  g_y2[N];
__device__ float  g_part[(size_t)FBLOCKS * N];   // 16 MB col partials
__device__ float  g_p2[(size_t)P2 * N];
__device__ float  g_cost[N];

// ============================================================
// 1) row norms of X and Y
// ============================================================
__global__ __launch_bounds__(256) void norms_kernel(const float* __restrict__ X,
                                                    const float* __restrict__ Y) {
    int r = blockIdx.x;
    const float* src = (r < N) ? (X + (size_t)r * D) : (Y + (size_t)(r - N) * D);
    float v = src[threadIdx.x];
    v *= v;
    __shared__ float sh[256];
    sh[threadIdx.x] = v;
    __syncthreads();
    for (int off = 128; off > 0; off >>= 1) {
        if (threadIdx.x < off) sh[threadIdx.x] += sh[threadIdx.x + off];
        __syncthreads();
    }
    if (threadIdx.x == 0) {
        if (r < N) g_x2[r] = sh[0];
        else       g_y2[r - N] = sh[0];
    }
}

// ============================================================
// 2) GEMM: C = sqrt(max(x2+y2-2XY^T,0)+1e-6), also E = exp(-C/lam) fp16
// ============================================================
#define GBM 128
#define GBN 128
#define GBK 16

__global__ __launch_bounds__(256) void cost_gemm(const float* __restrict__ X,
                                                 const float* __restrict__ Y) {
    __shared__ float Xs[GBK][GBM + 4];
    __shared__ float Ys[GBK][GBN + 4];

    const int tid = threadIdx.x;
    const int bm = blockIdx.y * GBM;
    const int bn = blockIdx.x * GBN;
    const int tx = tid & 15;
    const int ty = tid >> 4;
    const int lr = tid >> 2;
    const int lk = (tid & 3) * 4;

    float acc[8][8];
#pragma unroll
    for (int i = 0; i < 8; i++)
#pragma unroll
        for (int j = 0; j < 8; j++) acc[i][j] = 0.0f;

    for (int k0 = 0; k0 < D; k0 += GBK) {
#pragma unroll
        for (int h = 0; h < 2; h++) {
            int row = lr + h * 64;
            float4 v = *(const float4*)&X[(size_t)(bm + row) * D + k0 + lk];
            Xs[lk + 0][row] = v.x; Xs[lk + 1][row] = v.y;
            Xs[lk + 2][row] = v.z; Xs[lk + 3][row] = v.w;
            float4 w = *(const float4*)&Y[(size_t)(bn + row) * D + k0 + lk];
            Ys[lk + 0][row] = w.x; Ys[lk + 1][row] = w.y;
            Ys[lk + 2][row] = w.z; Ys[lk + 3][row] = w.w;
        }
        __syncthreads();

#pragma unroll
        for (int k = 0; k < GBK; k++) {
            float a[8], b[8];
            *(float4*)&a[0] = *(const float4*)&Xs[k][ty * 8];
            *(float4*)&a[4] = *(const float4*)&Xs[k][ty * 8 + 4];
            *(float4*)&b[0] = *(const float4*)&Ys[k][tx * 8];
            *(float4*)&b[4] = *(const float4*)&Ys[k][tx * 8 + 4];
#pragma unroll
            for (int i = 0; i < 8; i++)
#pragma unroll
                for (int j = 0; j < 8; j++) acc[i][j] = fmaf(a[i], b[j], acc[i][j]);
        }
        __syncthreads();
    }

    float x2[8], y2[8];
#pragma unroll
    for (int i = 0; i < 8; i++) x2[i] = g_x2[bm + ty * 8 + i];
#pragma unroll
    for (int j = 0; j < 8; j++) y2[j] = g_y2[bn + tx * 8 + j];

#pragma unroll
    for (int i = 0; i < 8; i++) {
        size_t row = (size_t)(bm + ty * 8 + i);
        float c[8];
#pragma unroll
        for (int j = 0; j < 8; j++) {
            float sq = x2[i] + y2[j] - 2.0f * acc[i][j];
            c[j] = sqrtf(fmaxf(sq, 0.0f) + 1e-6f);
        }
        float* crow = g_C + row * N + bn + tx * 8;
        *(float4*)&crow[0] = make_float4(c[0], c[1], c[2], c[3]);
        *(float4*)&crow[4] = make_float4(c[4], c[5], c[6], c[7]);

        __half2 h0 = __floats2half2_rn(__expf(-c[0] * INV_LAM), __expf(-c[1] * INV_LAM));
        __half2 h1 = __floats2half2_rn(__expf(-c[2] * INV_LAM), __expf(-c[3] * INV_LAM));
        __half2 h2 = __floats2half2_rn(__expf(-c[4] * INV_LAM), __expf(-c[5] * INV_LAM));
        __half2 h3 = __floats2half2_rn(__expf(-c[6] * INV_LAM), __expf(-c[7] * INV_LAM));
        uint4 pk;
        pk.x = *(unsigned*)&h0; pk.y = *(unsigned*)&h1;
        pk.z = *(unsigned*)&h2; pk.w = *(unsigned*)&h3;
        *(uint4*)(g_E + row * N + bn + tx * 8) = pk;
    }
}

// ============================================================
// 3) init Eg = 1
// ============================================================
__global__ void init_g() {
    int j = blockIdx.x * 256 + threadIdx.x;
    g_Eg[j] = 1.0f;
}

// ============================================================
// 4) FUSED pass, two-phase chunk version (256 thr, 32 cols/thr):
//    phase 1: 16 independent row-dots (fully pipelined loads),
//             ONE barrier for the whole chunk.
//    phase 2: re-read chunk (L2-resident, ~74MB across chip) and
//             accumulate column partials with known ef[r].
// ============================================================
__global__ __launch_bounds__(256) void fused_pass() {
    __shared__ float sEg[N];            // 32 KB
    __shared__ float swarp[FROWS][8];
    const int tid = threadIdx.x;
    const int lane = tid & 31;
    const int wid = tid >> 5;

    for (int k = tid; k < N; k += 256) sEg[k] = g_Eg[k];
    __syncthreads();

    // thread's 32 columns: k*2048 + tid*8 + c, k in {0..3}
    float eg[4][8];
#pragma unroll
    for (int k = 0; k < 4; k++)
#pragma unroll
        for (int c = 0; c < 8; c++) eg[k][c] = sEg[k * 2048 + tid * 8 + c];

    const int i0 = blockIdx.x * FROWS;
    const __half* __restrict__ Ebase = g_E + (size_t)i0 * N;

    // ---------- phase 1: all row dots, no inter-row deps ----------
#pragma unroll
    for (int r = 0; r < FROWS; r++) {
        const __half* __restrict__ row = Ebase + (size_t)r * N;
        uint4 v[4];
#pragma unroll
        for (int k = 0; k < 4; k++)
            v[k] = *(const uint4*)(row + k * 2048 + tid * 8);
        float a0 = 0.0f, a1 = 0.0f;
#pragma unroll
        for (int k = 0; k < 4; k++) {
            const __half2* hp = (const __half2*)&v[k];
            float2 f0 = __half22float2(hp[0]);
            float2 f1 = __half22float2(hp[1]);
            float2 f2 = __half22float2(hp[2]);
            float2 f3 = __half22float2(hp[3]);
            a0 = fmaf(f0.x, eg[k][0], a0);
            a1 = fmaf(f0.y, eg[k][1], a1);
            a0 = fmaf(f1.x, eg[k][2], a0);
            a1 = fmaf(f1.y, eg[k][3], a1);
            a0 = fmaf(f2.x, eg[k][4], a0);
            a1 = fmaf(f2.y, eg[k][5], a1);
            a0 = fmaf(f3.x, eg[k][6], a0);
            a1 = fmaf(f3.y, eg[k][7], a1);
        }
        float p = a0 + a1;
#pragma unroll
        for (int o = 16; o > 0; o >>= 1)
            p += __shfl_down_sync(0xffffffffu, p, o);
        if (lane == 0) swarp[r][wid] = p;
    }
    __syncthreads();

    // every thread computes all 16 ef values (redundant; no 2nd barrier)
    float ef[FROWS];
#pragma unroll
    for (int r = 0; r < FROWS; r++) {
        float s = swarp[r][0] + swarp[r][1] + swarp[r][2] + swarp[r][3]
                + swarp[r][4] + swarp[r][5] + swarp[r][6] + swarp[r][7];
        ef[r] = INV_N / s;
        if (tid == r) g_s[i0 + r] = s;   // 16 threads write the 16 sums
    }

    // ---------- phase 2: re-read chunk (L2 hot), accumulate partials ----------
    float acc[4][8];
#pragma unroll
    for (int k = 0; k < 4; k++)
#pragma unroll
        for (int c = 0; c < 8; c++) acc[k][c] = 0.0f;

#pragma unroll
    for (int r = 0; r < FROWS; r++) {
        const __half* __restrict__ row = Ebase + (size_t)r * N;
        uint4 v[4];
#pragma unroll
        for (int k = 0; k < 4; k++)
            v[k] = *(const uint4*)(row + k * 2048 + tid * 8);
        const float e = ef[r];
#pragma unroll
        for (int k = 0; k < 4; k++) {
            const __half2* hp = (const __half2*)&v[k];
            float2 f0 = __half22float2(hp[0]);
            float2 f1 = __half22float2(hp[1]);
            float2 f2 = __half22float2(hp[2]);
            float2 f3 = __half22float2(hp[3]);
            acc[k][0] = fmaf(f0.x, e, acc[k][0]);
            acc[k][1] = fmaf(f0.y, e, acc[k][1]);
            acc[k][2] = fmaf(f1.x, e, acc[k][2]);
            acc[k][3] = fmaf(f1.y, e, acc[k][3]);
            acc[k][4] = fmaf(f2.x, e, acc[k][4]);
            acc[k][5] = fmaf(f2.y, e, acc[k][5]);
            acc[k][6] = fmaf(f3.x, e, acc[k][6]);
            acc[k][7] = fmaf(f3.y, e, acc[k][7]);
        }
    }

    float* part = g_part + (size_t)blockIdx.x * N;
#pragma unroll
    for (int k = 0; k < 4; k++) {
        *(float4*)&part[k * 2048 + tid * 8]     = make_float4(acc[k][0], acc[k][1], acc[k][2], acc[k][3]);
        *(float4*)&part[k * 2048 + tid * 8 + 4] = make_float4(acc[k][4], acc[k][5], acc[k][6], acc[k][7]);
    }
}

// ============================================================
// 5) combine stage 1: sum 32 of 512 partials -> g_p2[16][N]
// ============================================================
__global__ __launch_bounds__(256) void combine1() {
    const int j = blockIdx.x * 256 + threadIdx.x;
    const int c0 = blockIdx.y * (FBLOCKS / P2);
    float s = 0.0f;
#pragma unroll 8
    for (int c = 0; c < FBLOCKS / P2; c++)
        s += g_part[(size_t)(c0 + c) * N + j];
    g_p2[(size_t)blockIdx.y * N + j] = s;
}

// ============================================================
// 6) combine stage 2: S'_j, Eg = (1/N)/S'
// ============================================================
__global__ __launch_bounds__(256) void combine2() {
    const int j = blockIdx.x * 256 + threadIdx.x;
    float s = 0.0f;
#pragma unroll
    for (int c = 0; c < P2; c++) s += g_p2[(size_t)c * N + j];
    g_S[j] = s;
    g_Eg[j] = INV_N / s;
}

// ============================================================
// 7) finalize f, g (logs only here)
// ============================================================
__global__ __launch_bounds__(256) void final_fg() {
    const int i = blockIdx.x * 256 + threadIdx.x;
    g_f[i] = NEG_LAM_LOGN - LAMF * logf(g_s[i]);
    g_g[i] = NEG_LAM_LOGN - LAMF * logf(g_S[i]);
}

// ============================================================
// 8) final: pi = exp((f_i + g_j - C)/lam) from fp32 C; row cost partials
//    NOTE: out+1 is only 4-byte aligned -> SCALAR stores for pi.
// ============================================================
__global__ __launch_bounds__(256) void pi_cost(float* __restrict__ out) {
    const int i = blockIdx.x;
    const int tid = threadIdx.x;
    const float fi = g_f[i];
    const float* __restrict__ Crow = g_C + (size_t)i * N;
    float* __restrict__ orow = out + 1 + (size_t)i * N;

    float acc = 0.0f;
#pragma unroll
    for (int k = 0; k < 8; k++) {
        int j = (k * 256 + tid) * 4;
        float4 C4 = *(const float4*)&Crow[j];
        float4 G4 = *(const float4*)&g_g[j];
        float px = __expf((fi + G4.x - C4.x) * INV_LAM);
        float py = __expf((fi + G4.y - C4.y) * INV_LAM);
        float pz = __expf((fi + G4.z - C4.z) * INV_LAM);
        float pw = __expf((fi + G4.w - C4.w) * INV_LAM);
        orow[j + 0] = px;
        orow[j + 1] = py;
        orow[j + 2] = pz;
        orow[j + 3] = pw;
        acc = fmaf(px, C4.x, acc);
        acc = fmaf(py, C4.y, acc);
        acc = fmaf(pz, C4.z, acc);
        acc = fmaf(pw, C4.w, acc);
    }
    __shared__ float sh[256];
    sh[tid] = acc;
    __syncthreads();
    for (int off = 128; off > 0; off >>= 1) {
        if (tid < off) sh[tid] += sh[tid + off];
        __syncthreads();
    }
    if (tid == 0) g_cost[i] = sh[0];
}

// ============================================================
// 9) deterministic final cost reduction
// ============================================================
__global__ __launch_bounds__(1024) void cost_reduce(float* __restrict__ out) {
    __shared__ float sh[1024];
    float a = 0.0f;
    for (int k = threadIdx.x; k < N; k += 1024) a += g_cost[k];
    sh[threadIdx.x] = a;
    __syncthreads();
    for (int off = 512; off > 0; off >>= 1) {
        if (threadIdx.x < off) sh[threadIdx.x] += sh[threadIdx.x + off];
        __syncthreads();
    }
    if (threadIdx.x == 0) out[0] = sh[0];
}

// ============================================================
extern "C" void kernel_launch(void* const* d_in, const int* in_sizes, int n_in,
                              void* d_out, int out_size) {
    const float* X = (const float*)d_in[0];
    const float* Y = (const float*)d_in[1];
    float* out = (float*)d_out;

    norms_kernel<<<2 * N, 256>>>(X, Y);
    cost_gemm<<<dim3(N / GBN, N / GBM), 256>>>(X, Y);
    init_g<<<N / 256, 256>>>();

    for (int it = 0; it < 50; it++) {
        fused_pass<<<FBLOCKS, 256>>>();
        combine1<<<dim3(N / 256, P2), 256>>>();
        combine2<<<N / 256, 256>>>();
    }

    final_fg<<<N / 256, 256>>>();
    pi_cost<<<N, 256>>>(out);
    cost_reduce<<<1, 1024>>>(out);
}

// round 9
// speedup vs baseline: 1.1708x; 1.1708x over previous
#include <cuda_runtime.h>
#include <cuda_fp16.h>
#include <cstdint>
#include <math.h>

#define N 8192
#define D 256
#define LAMF 10.0f
#define INV_LAM 0.1f
#define NEG_LAM_LOGN (-90.109133472792885f)
#define INV_N 1.220703125e-4f     // 1/8192

#define SROWS 4                   // rows per sub-chunk (one smem buffer)
#define SUBS 4                    // sub-chunks per block
#define BROWS (SROWS * SUBS)      // 16 rows per block
#define FBLOCKS (N / BROWS)       // 512 partials
#define P2 16
#define SMEM_BYTES (2 * SROWS * N * 2)   // 131072: ring of 2 sub-chunk buffers

// ---- scratch (static device globals; no allocation allowed) ----
__device__ float  g_C[(size_t)N * N];   // fp32 cost matrix (final pass only)
__device__ __half g_E[(size_t)N * N];   // exp(-C/lam) fp16 (iteration passes)
__device__ float  g_f[N];
__device__ float  g_g[N];
__device__ float  g_s[N];               // row sums s_i
__device__ float  g_S[N];               // col sums S'_j
__device__ float  g_Eg[N];              // exp(g/lam) = (1/N)/S'
__device__ float  g_x2[N];
__device__ float  g_y2[N];
__device__ float  g_part[(size_t)FBLOCKS * N];   // 16 MB col partials
__device__ float  g_p2[(size_t)P2 * N];
__device__ float  g_cost[N];

// ============================================================
// 1) row norms of X and Y
// ============================================================
__global__ __launch_bounds__(256) void norms_kernel(const float* __restrict__ X,
                                                    const float* __restrict__ Y) {
    int r = blockIdx.x;
    const float* src = (r < N) ? (X + (size_t)r * D) : (Y + (size_t)(r - N) * D);
    float v = src[threadIdx.x];
    v *= v;
    __shared__ float sh[256];
    sh[threadIdx.x] = v;
    __syncthreads();
    for (int off = 128; off > 0; off >>= 1) {
        if (threadIdx.x < off) sh[threadIdx.x] += sh[threadIdx.x + off];
        __syncthreads();
    }
    if (threadIdx.x == 0) {
        if (r < N) g_x2[r] = sh[0];
        else       g_y2[r - N] = sh[0];
    }
}

// ============================================================
// 2) GEMM: C = sqrt(max(x2+y2-2XY^T,0)+1e-6), also E = exp(-C/lam) fp16
// ============================================================
#define GBM 128
#define GBN 128
#define GBK 16

__global__ __launch_bounds__(256) void cost_gemm(const float* __restrict__ X,
                                                 const float* __restrict__ Y) {
    __shared__ float Xs[GBK][GBM + 4];
    __shared__ float Ys[GBK][GBN + 4];

    const int tid = threadIdx.x;
    const int bm = blockIdx.y * GBM;
    const int bn = blockIdx.x * GBN;
    const int tx = tid & 15;
    const int ty = tid >> 4;
    const int lr = tid >> 2;
    const int lk = (tid & 3) * 4;

    float acc[8][8];
#pragma unroll
    for (int i = 0; i < 8; i++)
#pragma unroll
        for (int j = 0; j < 8; j++) acc[i][j] = 0.0f;

    for (int k0 = 0; k0 < D; k0 += GBK) {
#pragma unroll
        for (int h = 0; h < 2; h++) {
            int row = lr + h * 64;
            float4 v = *(const float4*)&X[(size_t)(bm + row) * D + k0 + lk];
            Xs[lk + 0][row] = v.x; Xs[lk + 1][row] = v.y;
            Xs[lk + 2][row] = v.z; Xs[lk + 3][row] = v.w;
            float4 w = *(const float4*)&Y[(size_t)(bn + row) * D + k0 + lk];
            Ys[lk + 0][row] = w.x; Ys[lk + 1][row] = w.y;
            Ys[lk + 2][row] = w.z; Ys[lk + 3][row] = w.w;
        }
        __syncthreads();

#pragma unroll
        for (int k = 0; k < GBK; k++) {
            float a[8], b[8];
            *(float4*)&a[0] = *(const float4*)&Xs[k][ty * 8];
            *(float4*)&a[4] = *(const float4*)&Xs[k][ty * 8 + 4];
            *(float4*)&b[0] = *(const float4*)&Ys[k][tx * 8];
            *(float4*)&b[4] = *(const float4*)&Ys[k][tx * 8 + 4];
#pragma unroll
            for (int i = 0; i < 8; i++)
#pragma unroll
                for (int j = 0; j < 8; j++) acc[i][j] = fmaf(a[i], b[j], acc[i][j]);
        }
        __syncthreads();
    }

    float x2[8], y2[8];
#pragma unroll
    for (int i = 0; i < 8; i++) x2[i] = g_x2[bm + ty * 8 + i];
#pragma unroll
    for (int j = 0; j < 8; j++) y2[j] = g_y2[bn + tx * 8 + j];

#pragma unroll
    for (int i = 0; i < 8; i++) {
        size_t row = (size_t)(bm + ty * 8 + i);
        float c[8];
#pragma unroll
        for (int j = 0; j < 8; j++) {
            float sq = x2[i] + y2[j] - 2.0f * acc[i][j];
            c[j] = sqrtf(fmaxf(sq, 0.0f) + 1e-6f);
        }
        float* crow = g_C + row * N + bn + tx * 8;
        *(float4*)&crow[0] = make_float4(c[0], c[1], c[2], c[3]);
        *(float4*)&crow[4] = make_float4(c[4], c[5], c[6], c[7]);

        __half2 h0 = __floats2half2_rn(__expf(-c[0] * INV_LAM), __expf(-c[1] * INV_LAM));
        __half2 h1 = __floats2half2_rn(__expf(-c[2] * INV_LAM), __expf(-c[3] * INV_LAM));
        __half2 h2 = __floats2half2_rn(__expf(-c[4] * INV_LAM), __expf(-c[5] * INV_LAM));
        __half2 h3 = __floats2half2_rn(__expf(-c[6] * INV_LAM), __expf(-c[7] * INV_LAM));
        uint4 pk;
        pk.x = *(unsigned*)&h0; pk.y = *(unsigned*)&h1;
        pk.z = *(unsigned*)&h2; pk.w = *(unsigned*)&h3;
        *(uint4*)(g_E + row * N + bn + tx * 8) = pk;
    }
}

// ============================================================
// 3) init Eg = 1
// ============================================================
__global__ void init_g() {
    int j = blockIdx.x * 256 + threadIdx.x;
    g_Eg[j] = 1.0f;
}

// ============================================================
// 4) FUSED pass with cp.async staging.
//    512 threads, 16 cols/thread. Ring of 2 sub-chunk buffers
//    (4 rows x 16KB each). All smem regions THREAD-PRIVATE ->
//    staging needs only per-thread cp.async.wait_group; one
//    __syncthreads per sub-chunk for the dot reduction.
// ============================================================
__device__ __forceinline__ void cp_async16(unsigned int dst, const void* src) {
    asm volatile("cp.async.cg.shared.global [%0], [%1], 16;" :: "r"(dst), "l"(src));
}

__device__ __forceinline__ float dot16(const uint4& va, const uint4& vb,
                                       const float* __restrict__ eg) {
    float a0 = 0.0f, a1 = 0.0f;
    const __half2* ha = (const __half2*)&va;
    const __half2* hb = (const __half2*)&vb;
#pragma unroll
    for (int q = 0; q < 4; q++) {
        float2 f = __half22float2(ha[q]);
        a0 = fmaf(f.x, eg[2 * q], a0);
        a1 = fmaf(f.y, eg[2 * q + 1], a1);
    }
#pragma unroll
    for (int q = 0; q < 4; q++) {
        float2 f = __half22float2(hb[q]);
        a0 = fmaf(f.x, eg[8 + 2 * q], a0);
        a1 = fmaf(f.y, eg[8 + 2 * q + 1], a1);
    }
    return a0 + a1;
}

__device__ __forceinline__ void acc16(const uint4& va, const uint4& vb,
                                      float e, float* __restrict__ acc) {
    const __half2* ha = (const __half2*)&va;
    const __half2* hb = (const __half2*)&vb;
#pragma unroll
    for (int q = 0; q < 4; q++) {
        float2 f = __half22float2(ha[q]);
        acc[2 * q]     = fmaf(f.x, e, acc[2 * q]);
        acc[2 * q + 1] = fmaf(f.y, e, acc[2 * q + 1]);
    }
#pragma unroll
    for (int q = 0; q < 4; q++) {
        float2 f = __half22float2(hb[q]);
        acc[8 + 2 * q]     = fmaf(f.x, e, acc[8 + 2 * q]);
        acc[8 + 2 * q + 1] = fmaf(f.y, e, acc[8 + 2 * q + 1]);
    }
}

extern __shared__ __half sE[];   // [2][SROWS][N]

__global__ __launch_bounds__(512) void fused_pass() {
    __shared__ float swarp[2][SROWS][16];
    const int tid = threadIdx.x;
    const int lane = tid & 31;
    const int wid = tid >> 5;
    const int i0 = blockIdx.x * BROWS;
    const int off = tid * 16;                 // this thread's 16 columns

    float eg[16];
#pragma unroll
    for (int q = 0; q < 4; q++)
        *(float4*)&eg[q * 4] = *(const float4*)&g_Eg[off + q * 4];

    float acc[16];
#pragma unroll
    for (int c = 0; c < 16; c++) acc[c] = 0.0f;

    const unsigned int sm_base = (unsigned int)__cvta_generic_to_shared(sE);

    // issue one row's loads (2 x 16B per thread) + commit a group
    auto issue_row = [&](int s, int r) {
        const __half* src = g_E + (size_t)(i0 + s * SROWS + r) * N + off;
        unsigned int dst = sm_base + (unsigned int)((((s & 1) * SROWS + r) * N + off) * 2);
        cp_async16(dst, src);
        cp_async16(dst + 16, src + 8);
        asm volatile("cp.async.commit_group;");
    };

    // prologue: stage sub-chunks 0 and 1 (groups 0..7)
#pragma unroll
    for (int s = 0; s < 2; s++)
#pragma unroll
        for (int r = 0; r < SROWS; r++) issue_row(s, r);

#pragma unroll 1
    for (int s = 0; s < SUBS; s++) {
        const int p = s & 1;
        const __half* buf = sE + (size_t)p * SROWS * N + off;

        // ---- dot phase: wait constants uniform (7-r) by construction ----
        {
            asm volatile("cp.async.wait_group 7;");
            uint4 va = *(const uint4*)(buf + 0 * N);
            uint4 vb = *(const uint4*)(buf + 0 * N + 8);
            float pr = dot16(va, vb, eg);
#pragma unroll
            for (int o = 16; o > 0; o >>= 1) pr += __shfl_down_sync(0xffffffffu, pr, o);
            if (lane == 0) swarp[p][0][wid] = pr;
        }
        {
            asm volatile("cp.async.wait_group 6;");
            uint4 va = *(const uint4*)(buf + 1 * N);
            uint4 vb = *(const uint4*)(buf + 1 * N + 8);
            float pr = dot16(va, vb, eg);
#pragma unroll
            for (int o = 16; o > 0; o >>= 1) pr += __shfl_down_sync(0xffffffffu, pr, o);
            if (lane == 0) swarp[p][1][wid] = pr;
        }
        {
            asm volatile("cp.async.wait_group 5;");
            uint4 va = *(const uint4*)(buf + 2 * N);
            uint4 vb = *(const uint4*)(buf + 2 * N + 8);
            float pr = dot16(va, vb, eg);
#pragma unroll
            for (int o = 16; o > 0; o >>= 1) pr += __shfl_down_sync(0xffffffffu, pr, o);
            if (lane == 0) swarp[p][2][wid] = pr;
        }
        {
            asm volatile("cp.async.wait_group 4;");
            uint4 va = *(const uint4*)(buf + 3 * N);
            uint4 vb = *(const uint4*)(buf + 3 * N + 8);
            float pr = dot16(va, vb, eg);
#pragma unroll
            for (int o = 16; o > 0; o >>= 1) pr += __shfl_down_sync(0xffffffffu, pr, o);
            if (lane == 0) swarp[p][3][wid] = pr;
        }
        __syncthreads();

        // ---- every thread computes ef[0..3] (redundant, no 2nd barrier) ----
        float ef[SROWS];
#pragma unroll
        for (int r = 0; r < SROWS; r++) {
            float sum = 0.0f;
#pragma unroll
            for (int w = 0; w < 16; w++) sum += swarp[p][r][w];
            ef[r] = INV_N / sum;
            if (tid == r) g_s[i0 + s * SROWS + r] = sum;
        }

        // ---- acc phase; refill slot r for sub-chunk s+2 right after use ----
#pragma unroll
        for (int r = 0; r < SROWS; r++) {
            uint4 va = *(const uint4*)(buf + r * N);
            uint4 vb = *(const uint4*)(buf + r * N + 8);
            acc16(va, vb, ef[r], acc);
            if (s + 2 < SUBS) issue_row(s + 2, r);
            else asm volatile("cp.async.commit_group;");   // empty group keeps wait constants uniform
        }
    }

    float* part = g_part + (size_t)blockIdx.x * N + off;
#pragma unroll
    for (int q = 0; q < 4; q++)
        *(float4*)&part[q * 4] = make_float4(acc[q * 4], acc[q * 4 + 1],
                                             acc[q * 4 + 2], acc[q * 4 + 3]);
}

// ============================================================
// 5) combine stage 1: sum 32 of 512 partials -> g_p2[16][N]
// ============================================================
__global__ __launch_bounds__(256) void combine1() {
    const int j = blockIdx.x * 256 + threadIdx.x;
    const int c0 = blockIdx.y * (FBLOCKS / P2);
    float s = 0.0f;
#pragma unroll 8
    for (int c = 0; c < FBLOCKS / P2; c++)
        s += g_part[(size_t)(c0 + c) * N + j];
    g_p2[(size_t)blockIdx.y * N + j] = s;
}

// ============================================================
// 6) combine stage 2: S'_j, Eg = (1/N)/S'
// ============================================================
__global__ __launch_bounds__(256) void combine2() {
    const int j = blockIdx.x * 256 + threadIdx.x;
    float s = 0.0f;
#pragma unroll
    for (int c = 0; c < P2; c++) s += g_p2[(size_t)c * N + j];
    g_S[j] = s;
    g_Eg[j] = INV_N / s;
}

// ============================================================
// 7) finalize f, g (logs only here)
// ============================================================
__global__ __launch_bounds__(256) void final_fg() {
    const int i = blockIdx.x * 256 + threadIdx.x;
    g_f[i] = NEG_LAM_LOGN - LAMF * logf(g_s[i]);
    g_g[i] = NEG_LAM_LOGN - LAMF * logf(g_S[i]);
}

// ============================================================
// 8) final: pi = exp((f_i + g_j - C)/lam) from fp32 C; row cost partials
//    NOTE: out+1 is only 4-byte aligned -> SCALAR stores for pi.
// ============================================================
__global__ __launch_bounds__(256) void pi_cost(float* __restrict__ out) {
    const int i = blockIdx.x;
    const int tid = threadIdx.x;
    const float fi = g_f[i];
    const float* __restrict__ Crow = g_C + (size_t)i * N;
    float* __restrict__ orow = out + 1 + (size_t)i * N;

    float acc = 0.0f;
#pragma unroll
    for (int k = 0; k < 8; k++) {
        int j = (k * 256 + tid) * 4;
        float4 C4 = *(const float4*)&Crow[j];
        float4 G4 = *(const float4*)&g_g[j];
        float px = __expf((fi + G4.x - C4.x) * INV_LAM);
        float py = __expf((fi + G4.y - C4.y) * INV_LAM);
        float pz = __expf((fi + G4.z - C4.z) * INV_LAM);
        float pw = __expf((fi + G4.w - C4.w) * INV_LAM);
        orow[j + 0] = px;
        orow[j + 1] = py;
        orow[j + 2] = pz;
        orow[j + 3] = pw;
        acc = fmaf(px, C4.x, acc);
        acc = fmaf(py, C4.y, acc);
        acc = fmaf(pz, C4.z, acc);
        acc = fmaf(pw, C4.w, acc);
    }
    __shared__ float sh[256];
    sh[tid] = acc;
    __syncthreads();
    for (int off = 128; off > 0; off >>= 1) {
        if (tid < off) sh[tid] += sh[tid + off];
        __syncthreads();
    }
    if (tid == 0) g_cost[i] = sh[0];
}

// ============================================================
// 9) deterministic final cost reduction
// ============================================================
__global__ __launch_bounds__(1024) void cost_reduce(float* __restrict__ out) {
    __shared__ float sh[1024];
    float a = 0.0f;
    for (int k = threadIdx.x; k < N; k += 1024) a += g_cost[k];
    sh[threadIdx.x] = a;
    __syncthreads();
    for (int off = 512; off > 0; off >>= 1) {
        if (threadIdx.x < off) sh[threadIdx.x] += sh[threadIdx.x + off];
        __syncthreads();
    }
    if (threadIdx.x == 0) out[0] = sh[0];
}

// ============================================================
extern "C" void kernel_launch(void* const* d_in, const int* in_sizes, int n_in,
                              void* d_out, int out_size) {
    const float* X = (const float*)d_in[0];
    const float* Y = (const float*)d_in[1];
    float* out = (float*)d_out;

    cudaFuncSetAttribute(fused_pass, cudaFuncAttributeMaxDynamicSharedMemorySize,
                         SMEM_BYTES);

    norms_kernel<<<2 * N, 256>>>(X, Y);
    cost_gemm<<<dim3(N / GBN, N / GBM), 256>>>(X, Y);
    init_g<<<N / 256, 256>>>();

    for (int it = 0; it < 50; it++) {
        fused_pass<<<FBLOCKS, 512, SMEM_BYTES>>>();
        combine1<<<dim3(N / 256, P2), 256>>>();
        combine2<<<N / 256, 256>>>();
    }

    final_fg<<<N / 256, 256>>>();
    pi_cost<<<N, 256>>>(out);
    cost_reduce<<<1, 1024>>>(out);
}

// round 10
// speedup vs baseline: 1.4819x; 1.2657x over previous
#include <cuda_runtime.h>
#include <cuda_fp16.h>
#include <cstdint>
#include <math.h>

#define N 8192
#define D 256
#define LAMF 10.0f
#define INV_LAM 0.1f
#define NEG_LAM_LOGN (-90.109133472792885f)
#define INV_N 1.220703125e-4f     // 1/8192

#define FROWS 16
#define FBLOCKS (N / FROWS)       // 512 row-chunks / partials
#define P2 16                     // second-stage partial count

// ---- scratch (static device globals; no allocation allowed) ----
__device__ float  g_C[(size_t)N * N];   // fp32 cost matrix (final pass only)
__device__ __half g_E[(size_t)N * N];   // exp(-C/lam) fp16 (quantizer input)
__device__ unsigned char g_E8[(size_t)N * N];   // u8 quantized E (iterations)
__device__ int    g_emax_bits;          // global max of E (float bits), zero-init
__device__ float  g_f[N];
__device__ float  g_g[N];
__device__ float  g_s[N];               // row sums s_i
__device__ float  g_S[N];               // col sums S'_j
__device__ float  g_Eg[N];              // exp(g/lam) = (1/N)/S'
__device__ float  g_x2[N];
__device__ float  g_y2[N];
__device__ float  g_part[(size_t)FBLOCKS * N];   // 16 MB col partials
__device__ float  g_p2[(size_t)P2 * N];
__device__ float  g_cost[N];

// ============================================================
// 1) row norms of X and Y
// ============================================================
__global__ __launch_bounds__(256) void norms_kernel(const float* __restrict__ X,
                                                    const float* __restrict__ Y) {
    int r = blockIdx.x;
    const float* src = (r < N) ? (X + (size_t)r * D) : (Y + (size_t)(r - N) * D);
    float v = src[threadIdx.x];
    v *= v;
    __shared__ float sh[256];
    sh[threadIdx.x] = v;
    __syncthreads();
    for (int off = 128; off > 0; off >>= 1) {
        if (threadIdx.x < off) sh[threadIdx.x] += sh[threadIdx.x + off];
        __syncthreads();
    }
    if (threadIdx.x == 0) {
        if (r < N) g_x2[r] = sh[0];
        else       g_y2[r - N] = sh[0];
    }
}

// ============================================================
// 2) GEMM: C = sqrt(max(x2+y2-2XY^T,0)+1e-6); E fp16; atomicMax(E)
// ============================================================
#define GBM 128
#define GBN 128
#define GBK 16

__global__ __launch_bounds__(256) void cost_gemm(const float* __restrict__ X,
                                                 const float* __restrict__ Y) {
    __shared__ float Xs[GBK][GBM + 4];
    __shared__ float Ys[GBK][GBN + 4];

    const int tid = threadIdx.x;
    const int bm = blockIdx.y * GBM;
    const int bn = blockIdx.x * GBN;
    const int tx = tid & 15;
    const int ty = tid >> 4;
    const int lr = tid >> 2;
    const int lk = (tid & 3) * 4;

    float acc[8][8];
#pragma unroll
    for (int i = 0; i < 8; i++)
#pragma unroll
        for (int j = 0; j < 8; j++) acc[i][j] = 0.0f;

    for (int k0 = 0; k0 < D; k0 += GBK) {
#pragma unroll
        for (int h = 0; h < 2; h++) {
            int row = lr + h * 64;
            float4 v = *(const float4*)&X[(size_t)(bm + row) * D + k0 + lk];
            Xs[lk + 0][row] = v.x; Xs[lk + 1][row] = v.y;
            Xs[lk + 2][row] = v.z; Xs[lk + 3][row] = v.w;
            float4 w = *(const float4*)&Y[(size_t)(bn + row) * D + k0 + lk];
            Ys[lk + 0][row] = w.x; Ys[lk + 1][row] = w.y;
            Ys[lk + 2][row] = w.z; Ys[lk + 3][row] = w.w;
        }
        __syncthreads();

#pragma unroll
        for (int k = 0; k < GBK; k++) {
            float a[8], b[8];
            *(float4*)&a[0] = *(const float4*)&Xs[k][ty * 8];
            *(float4*)&a[4] = *(const float4*)&Xs[k][ty * 8 + 4];
            *(float4*)&b[0] = *(const float4*)&Ys[k][tx * 8];
            *(float4*)&b[4] = *(const float4*)&Ys[k][tx * 8 + 4];
#pragma unroll
            for (int i = 0; i < 8; i++)
#pragma unroll
                for (int j = 0; j < 8; j++) acc[i][j] = fmaf(a[i], b[j], acc[i][j]);
        }
        __syncthreads();
    }

    float x2[8], y2[8];
#pragma unroll
    for (int i = 0; i < 8; i++) x2[i] = g_x2[bm + ty * 8 + i];
#pragma unroll
    for (int j = 0; j < 8; j++) y2[j] = g_y2[bn + tx * 8 + j];

    float emax = 0.0f;
#pragma unroll
    for (int i = 0; i < 8; i++) {
        size_t row = (size_t)(bm + ty * 8 + i);
        float c[8], e[8];
#pragma unroll
        for (int j = 0; j < 8; j++) {
            float sq = x2[i] + y2[j] - 2.0f * acc[i][j];
            c[j] = sqrtf(fmaxf(sq, 0.0f) + 1e-6f);
            e[j] = __expf(-c[j] * INV_LAM);
            emax = fmaxf(emax, e[j]);
        }
        float* crow = g_C + row * N + bn + tx * 8;
        *(float4*)&crow[0] = make_float4(c[0], c[1], c[2], c[3]);
        *(float4*)&crow[4] = make_float4(c[4], c[5], c[6], c[7]);

        __half2 h0 = __floats2half2_rn(e[0], e[1]);
        __half2 h1 = __floats2half2_rn(e[2], e[3]);
        __half2 h2 = __floats2half2_rn(e[4], e[5]);
        __half2 h3 = __floats2half2_rn(e[6], e[7]);
        uint4 pk;
        pk.x = *(unsigned*)&h0; pk.y = *(unsigned*)&h1;
        pk.z = *(unsigned*)&h2; pk.w = *(unsigned*)&h3;
        *(uint4*)(g_E + row * N + bn + tx * 8) = pk;
    }
    // deterministic global max (bit-max on positive floats)
#pragma unroll
    for (int o = 16; o > 0; o >>= 1)
        emax = fmaxf(emax, __shfl_xor_sync(0xffffffffu, emax, o));
    if ((tid & 31) == 0) atomicMax(&g_emax_bits, __float_as_int(emax));
}

// ============================================================
// 3) quantize E fp16 -> u8:  q = round(E / (emax/255))
// ============================================================
__global__ __launch_bounds__(256) void quantize_E() {
    const float r = 255.0f / __int_as_float(g_emax_bits);
    size_t base = ((size_t)blockIdx.x * 256 + threadIdx.x) * 16;
    uint4 ha = *(const uint4*)(g_E + base);
    uint4 hb = *(const uint4*)(g_E + base + 8);
    const __half2* pa = (const __half2*)&ha;
    const __half2* pb = (const __half2*)&hb;
    unsigned ow[4];
#pragma unroll
    for (int k = 0; k < 2; k++) {
        float2 f0 = __half22float2(pa[k * 2]);
        float2 f1 = __half22float2(pa[k * 2 + 1]);
        unsigned q0 = (unsigned)(f0.x * r + 0.5f);
        unsigned q1 = (unsigned)(f0.y * r + 0.5f);
        unsigned q2 = (unsigned)(f1.x * r + 0.5f);
        unsigned q3 = (unsigned)(f1.y * r + 0.5f);
        ow[k] = q0 | (q1 << 8) | (q2 << 16) | (q3 << 24);
    }
#pragma unroll
    for (int k = 0; k < 2; k++) {
        float2 f0 = __half22float2(pb[k * 2]);
        float2 f1 = __half22float2(pb[k * 2 + 1]);
        unsigned q0 = (unsigned)(f0.x * r + 0.5f);
        unsigned q1 = (unsigned)(f0.y * r + 0.5f);
        unsigned q2 = (unsigned)(f1.x * r + 0.5f);
        unsigned q3 = (unsigned)(f1.y * r + 0.5f);
        ow[2 + k] = q0 | (q1 << 8) | (q2 << 16) | (q3 << 24);
    }
    uint4 pk; pk.x = ow[0]; pk.y = ow[1]; pk.z = ow[2]; pk.w = ow[3];
    *(uint4*)(g_E8 + base) = pk;
}

// ============================================================
// 4) init Eg = 1
// ============================================================
__global__ void init_g() {
    int j = blockIdx.x * 256 + threadIdx.x;
    g_Eg[j] = 1.0f;
}

// ============================================================
// 5) FUSED pass on u8 E (R4 structure): 256 thr, 32 cols/thread,
//    register double-buffer, ONE barrier/row (double-buffered swarp
//    + redundant smem sum). PRMT+FADD dequant (exact).
// ============================================================
__device__ __forceinline__ float dq(unsigned w, int sel) {
    return __uint_as_float(__byte_perm(w, 0x4B000000u, sel)) - 8388608.0f;
}

__global__ __launch_bounds__(256) void fused_pass() {
    __shared__ float sEg[N];          // 32 KB
    __shared__ float swarp[2][8];
    const int tid = threadIdx.x;
    const int lane = tid & 31;
    const int wid = tid >> 5;

    for (int k = tid; k < N; k += 256) sEg[k] = g_Eg[k];
    __syncthreads();

    const int off = tid * 32;         // 32 consecutive columns per thread
    float eg[32];
#pragma unroll
    for (int q = 0; q < 8; q++)
        *(float4*)&eg[q * 4] = *(const float4*)&sEg[off + q * 4];

    const float a = __int_as_float(g_emax_bits) * (1.0f / 255.0f);
    const int i0 = blockIdx.x * FROWS;

    float acc[32];
#pragma unroll
    for (int c = 0; c < 32; c++) acc[c] = 0.0f;

    uint4 v[2];
    {
        const unsigned char* base = g_E8 + (size_t)i0 * N + off;
        v[0] = *(const uint4*)base;
        v[1] = *(const uint4*)(base + 16);
    }

#pragma unroll 1
    for (int r = 0; r < FROWS; r++) {
        const unsigned* w = (const unsigned*)v;
        // ---- dot with Eg ----
        float a0 = 0.0f, a1 = 0.0f;
#pragma unroll
        for (int k = 0; k < 8; k++) {
            a0 = fmaf(dq(w[k], 0x7440), eg[k * 4 + 0], a0);
            a1 = fmaf(dq(w[k], 0x7441), eg[k * 4 + 1], a1);
            a0 = fmaf(dq(w[k], 0x7442), eg[k * 4 + 2], a0);
            a1 = fmaf(dq(w[k], 0x7443), eg[k * 4 + 3], a1);
        }
        float p = a0 + a1;
#pragma unroll
        for (int o = 16; o > 0; o >>= 1)
            p += __shfl_down_sync(0xffffffffu, p, o);
        if (lane == 0) swarp[r & 1][wid] = p;

        // ---- preload next row before the barrier ----
        uint4 vn[2];
        {
            int rn = (r + 1 < FROWS) ? (r + 1) : r;
            const unsigned char* bp = g_E8 + (size_t)(i0 + rn) * N + off;
            vn[0] = *(const uint4*)bp;
            vn[1] = *(const uint4*)(bp + 16);
        }
        __syncthreads();

        // ---- redundant per-thread sum of 8 warp partials ----
        float sum = swarp[r & 1][0] + swarp[r & 1][1] + swarp[r & 1][2] + swarp[r & 1][3]
                  + swarp[r & 1][4] + swarp[r & 1][5] + swarp[r & 1][6] + swarp[r & 1][7];
        float s = a * sum;
        if (tid == r) g_s[i0 + r] = s;
        const float ef = INV_N / s;

        // ---- accumulate column partials (same registers) ----
#pragma unroll
        for (int k = 0; k < 8; k++) {
            acc[k * 4 + 0] = fmaf(dq(w[k], 0x7440), ef, acc[k * 4 + 0]);
            acc[k * 4 + 1] = fmaf(dq(w[k], 0x7441), ef, acc[k * 4 + 1]);
            acc[k * 4 + 2] = fmaf(dq(w[k], 0x7442), ef, acc[k * 4 + 2]);
            acc[k * 4 + 3] = fmaf(dq(w[k], 0x7443), ef, acc[k * 4 + 3]);
        }
        v[0] = vn[0];
        v[1] = vn[1];
    }

    float* part = g_part + (size_t)blockIdx.x * N + off;
#pragma unroll
    for (int q = 0; q < 8; q++)
        *(float4*)&part[q * 4] = make_float4(a * acc[q * 4],     a * acc[q * 4 + 1],
                                             a * acc[q * 4 + 2], a * acc[q * 4 + 3]);
}

// ============================================================
// 6) combine stage 1: sum 32 of 512 partials -> g_p2[16][N]
// ============================================================
__global__ __launch_bounds__(256) void combine1() {
    const int j = blockIdx.x * 256 + threadIdx.x;
    const int c0 = blockIdx.y * (FBLOCKS / P2);
    float s = 0.0f;
#pragma unroll 8
    for (int c = 0; c < FBLOCKS / P2; c++)
        s += g_part[(size_t)(c0 + c) * N + j];
    g_p2[(size_t)blockIdx.y * N + j] = s;
}

// ============================================================
// 7) combine stage 2: S'_j, Eg = (1/N)/S'
// ============================================================
__global__ __launch_bounds__(256) void combine2() {
    const int j = blockIdx.x * 256 + threadIdx.x;
    float s = 0.0f;
#pragma unroll
    for (int c = 0; c < P2; c++) s += g_p2[(size_t)c * N + j];
    g_S[j] = s;
    g_Eg[j] = INV_N / s;
}

// ============================================================
// 8) finalize f, g (logs only here)
// ============================================================
__global__ __launch_bounds__(256) void final_fg() {
    const int i = blockIdx.x * 256 + threadIdx.x;
    g_f[i] = NEG_LAM_LOGN - LAMF * logf(g_s[i]);
    g_g[i] = NEG_LAM_LOGN - LAMF * logf(g_S[i]);
}

// ============================================================
// 9) final: pi = exp((f_i + g_j - C)/lam) from fp32 C; row cost partials
//    NOTE: out+1 is only 4-byte aligned -> SCALAR stores for pi.
// ============================================================
__global__ __launch_bounds__(256) void pi_cost(float* __restrict__ out) {
    const int i = blockIdx.x;
    const int tid = threadIdx.x;
    const float fi = g_f[i];
    const float* __restrict__ Crow = g_C + (size_t)i * N;
    float* __restrict__ orow = out + 1 + (size_t)i * N;

    float acc = 0.0f;
#pragma unroll
    for (int k = 0; k < 8; k++) {
        int j = (k * 256 + tid) * 4;
        float4 C4 = *(const float4*)&Crow[j];
        float4 G4 = *(const float4*)&g_g[j];
        float px = __expf((fi + G4.x - C4.x) * INV_LAM);
        float py = __expf((fi + G4.y - C4.y) * INV_LAM);
        float pz = __expf((fi + G4.z - C4.z) * INV_LAM);
        float pw = __expf((fi + G4.w - C4.w) * INV_LAM);
        orow[j + 0] = px;
        orow[j + 1] = py;
        orow[j + 2] = pz;
        orow[j + 3] = pw;
        acc = fmaf(px, C4.x, acc);
        acc = fmaf(py, C4.y, acc);
        acc = fmaf(pz, C4.z, acc);
        acc = fmaf(pw, C4.w, acc);
    }
    __shared__ float sh[256];
    sh[tid] = acc;
    __syncthreads();
    for (int off = 128; off > 0; off >>= 1) {
        if (tid < off) sh[tid] += sh[tid + off];
        __syncthreads();
    }
    if (tid == 0) g_cost[i] = sh[0];
}

// ============================================================
// 10) deterministic final cost reduction
// ============================================================
__global__ __launch_bounds__(1024) void cost_reduce(float* __restrict__ out) {
    __shared__ float sh[1024];
    float a = 0.0f;
    for (int k = threadIdx.x; k < N; k += 1024) a += g_cost[k];
    sh[threadIdx.x] = a;
    __syncthreads();
    for (int off = 512; off > 0; off >>= 1) {
        if (threadIdx.x < off) sh[threadIdx.x] += sh[threadIdx.x + off];
        __syncthreads();
    }
    if (threadIdx.x == 0) out[0] = sh[0];
}

// ============================================================
extern "C" void kernel_launch(void* const* d_in, const int* in_sizes, int n_in,
                              void* d_out, int out_size) {
    const float* X = (const float*)d_in[0];
    const float* Y = (const float*)d_in[1];
    float* out = (float*)d_out;

    norms_kernel<<<2 * N, 256>>>(X, Y);
    cost_gemm<<<dim3(N / GBN, N / GBM), 256>>>(X, Y);
    quantize_E<<<(int)(((size_t)N * N) / (256 * 16)), 256>>>();
    init_g<<<N / 256, 256>>>();

    for (int it = 0; it < 50; it++) {
        fused_pass<<<FBLOCKS, 256>>>();
        combine1<<<dim3(N / 256, P2), 256>>>();
        combine2<<<N / 256, 256>>>();
    }

    final_fg<<<N / 256, 256>>>();
    pi_cost<<<N, 256>>>(out);
    cost_reduce<<<1, 1024>>>(out);
}